// round 12
// baseline (speedup 1.0000x reference)
#include <cuda_runtime.h>
#include <math.h>

#define Bx  16
#define Lx  32768
#define Hx  64
#define NSx 16
#define DMx 32
#define CHx 256
#define NCx (Lx/CHx)   // 128 chunks

typedef unsigned long long ull;

// ---- scratch (static device arrays: allocation-free) ----
__device__ __align__(16) float g_u[Bx*Lx*Hx];             // gelu(x@W_lin+b), [B,L,H]
__device__ __align__(16) float g_st_re[Bx*NCx*Hx*NSx];    // per-chunk local final states
__device__ __align__(16) float g_st_im[Bx*NCx*Hx*NSx];
__device__ __align__(16) float g_ca_re[Bx*NCx*Hx*NSx];    // carry-in per chunk
__device__ __align__(16) float g_ca_im[Bx*NCx*Hx*NSx];
__device__ float g_wre[Hx*NSx], g_wim[Hx*NSx];     // w = exp(dt*A)
__device__ float g_c2re[Hx*NSx], g_c2im[Hx*NSx];   // 2*Re/-2*Im of C*(w-1)/A
__device__ float g_wcre[Hx*NSx], g_wcim[Hx*NSx];   // w^CH
__device__ float g_gam[Bx*Hx], g_bet[Bx*Hx];       // FiLM params

// ---- packed f32x2 helpers (sm_103a) ----
__device__ __forceinline__ ull pk(float lo, float hi) {
    ull r; asm("mov.b64 %0, {%1,%2};" : "=l"(r) : "f"(lo), "f"(hi)); return r;
}
__device__ __forceinline__ void upk(ull v, float& lo, float& hi) {
    asm("mov.b64 {%0,%1}, %2;" : "=f"(lo), "=f"(hi) : "l"(v));
}
__device__ __forceinline__ ull fma2(ull a, ull b, ull c) {
    ull d; asm("fma.rn.f32x2 %0, %1, %2, %3;" : "=l"(d) : "l"(a), "l"(b), "l"(c)); return d;
}
__device__ __forceinline__ ull mul2(ull a, ull b) {
    ull d; asm("mul.rn.f32x2 %0, %1, %2;" : "=l"(d) : "l"(a), "l"(b)); return d;
}
__device__ __forceinline__ ull add2(ull a, ull b) {
    ull d; asm("add.rn.f32x2 %0, %1, %2;" : "=l"(d) : "l"(a), "l"(b)); return d;
}

__device__ __forceinline__ float gelu_t(float x) {
    float x3 = x * x * x;
    float t  = tanhf(0.7978845608028654f * fmaf(0.044715f, x3, x));
    return 0.5f * x * (1.0f + t);
}
__device__ __forceinline__ float gelu_fast(float x) {
    float x3  = x * x * x;
    float arg = 0.7978845608028654f * fmaf(0.044715f, x3, x);
    float t;
    asm("tanh.approx.f32 %0, %1;" : "=f"(t) : "f"(arg));
    return 0.5f * x * (1.0f + t);
}

// ============================================================
// K0: SSM constants (fp64 setup) + cond-MLP + FiLM projection
// ============================================================
__global__ void k_setup(const float* __restrict__ cp,
                        const float* __restrict__ W0, const float* __restrict__ b0,
                        const float* __restrict__ W1, const float* __restrict__ b1,
                        const float* __restrict__ W2, const float* __restrict__ b2,
                        const float* __restrict__ log_dt,
                        const float* __restrict__ A_re, const float* __restrict__ A_im,
                        const float* __restrict__ C_re, const float* __restrict__ C_im,
                        const float* __restrict__ W_film, const float* __restrict__ b_film)
{
    int tid = threadIdx.x;

    if (tid < Hx * NSx) {
        int h = tid / NSx;
        double dt = exp((double)log_dt[h]);
        double ar = (double)A_re[tid], ai = (double)A_im[tid];
        double dr = dt * ar, di = dt * ai;
        double er = exp(dr);
        double wr = er * cos(di), wi = er * sin(di);
        g_wre[tid] = (float)wr;
        g_wim[tid] = (float)wi;
        double Er = wr - 1.0, Ei = wi;
        double a2 = ar * ar + ai * ai;
        double qr = (Er * ar + Ei * ai) / a2;
        double qi = (Ei * ar - Er * ai) / a2;
        double cr = (double)C_re[tid], ci = (double)C_im[tid];
        double Ctr = cr * qr - ci * qi;
        double Cti = cr * qi + ci * qr;
        g_c2re[tid] = (float)( 2.0 * Ctr);
        g_c2im[tid] = (float)(-2.0 * Cti);
        double drC = dr * (double)CHx, diC = di * (double)CHx;
        double erC = exp(drC);
        g_wcre[tid] = (float)(erC * cos(diC));
        g_wcim[tid] = (float)(erC * sin(diC));
    }

    __shared__ float s1[Bx * DMx];
    __shared__ float s2[Bx * DMx];
    if (tid < Bx * DMx) {
        int b = tid / DMx, d = tid % DMx;
        float v = b0[d] + cp[b*2 + 0] * W0[0*DMx + d] + cp[b*2 + 1] * W0[1*DMx + d];
        s1[tid] = gelu_t(v);
    }
    __syncthreads();
    if (tid < Bx * DMx) {
        int b = tid / DMx, d = tid % DMx;
        float v = b1[d];
        #pragma unroll
        for (int k = 0; k < DMx; k++) v = fmaf(s1[b*DMx + k], W1[k*DMx + d], v);
        s2[tid] = gelu_t(v);
    }
    __syncthreads();
    if (tid < Bx * DMx) {
        int b = tid / DMx, d = tid % DMx;
        float v = b2[d];
        #pragma unroll
        for (int k = 0; k < DMx; k++) v = fmaf(s2[b*DMx + k], W2[k*DMx + d], v);
        s1[tid] = gelu_t(v);
    }
    __syncthreads();
    for (int j = tid; j < Bx * 2 * Hx; j += blockDim.x) {
        int b = j / (2 * Hx), o = j % (2 * Hx);
        float v = b_film[o];
        #pragma unroll
        for (int k = 0; k < DMx; k++) v = fmaf(s1[b*DMx + k], W_film[k*2*Hx + o], v);
        if (o < Hx) g_gam[b*Hx + o] = v;
        else        g_bet[b*Hx + (o - Hx)] = v;
    }
}

// ============================================================
// K1: u = gelu(x @ W_lin + b_lin) — 64x64 tile, f32x2 packed FMA
// ============================================================
__global__ __launch_bounds__(128) void k_linear(const float* __restrict__ x,
                                                const float* __restrict__ Wl,
                                                const float* __restrict__ bl)
{
    __shared__ float sxT[64][68];
    __shared__ __align__(16) float sW[64 * 64];
    int tid = threadIdx.x;
    int r0  = blockIdx.x * 64;

    #pragma unroll
    for (int it = 0; it < 8; it++) {
        int i = tid + it * 128;
        *(float4*)(sW + i * 4) = *(const float4*)(Wl + i * 4);
    }
    #pragma unroll
    for (int it = 0; it < 8; it++) {
        int idx = tid + it * 128;
        int row = idx >> 4;
        int kg  = idx & 15;
        float4 v = *(const float4*)(x + (size_t)(r0 + row) * 64 + kg * 4);
        sxT[kg*4 + 0][row] = v.x;
        sxT[kg*4 + 1][row] = v.y;
        sxT[kg*4 + 2][row] = v.z;
        sxT[kg*4 + 3][row] = v.w;
    }
    __syncthreads();

    int tr = tid >> 3;
    int tc = tid & 7;
    ull acc[4][4];
    #pragma unroll
    for (int i = 0; i < 4; i++)
        #pragma unroll
        for (int j = 0; j < 4; j++) acc[i][j] = 0ull;

    #pragma unroll 4
    for (int k = 0; k < 64; k++) {
        float4 a = *(const float4*)(&sxT[k][tr * 4]);
        ull aa[4];
        aa[0] = pk(a.x, a.x); aa[1] = pk(a.y, a.y);
        aa[2] = pk(a.z, a.z); aa[3] = pk(a.w, a.w);
        const float* wrow = &sW[k * 64 + tc * 8];
        ull w0 = *(const ull*)(wrow + 0);
        ull w1 = *(const ull*)(wrow + 2);
        ull w2 = *(const ull*)(wrow + 4);
        ull w3 = *(const ull*)(wrow + 6);
        #pragma unroll
        for (int i = 0; i < 4; i++) {
            acc[i][0] = fma2(aa[i], w0, acc[i][0]);
            acc[i][1] = fma2(aa[i], w1, acc[i][1]);
            acc[i][2] = fma2(aa[i], w2, acc[i][2]);
            acc[i][3] = fma2(aa[i], w3, acc[i][3]);
        }
    }

    float bb[8];
    #pragma unroll
    for (int j = 0; j < 8; j++) bb[j] = bl[tc * 8 + j];
    #pragma unroll
    for (int i = 0; i < 4; i++) {
        float v[8];
        #pragma unroll
        for (int j = 0; j < 4; j++) upk(acc[i][j], v[2*j], v[2*j+1]);
        float4 o0, o1;
        o0.x = gelu_fast(v[0] + bb[0]); o0.y = gelu_fast(v[1] + bb[1]);
        o0.z = gelu_fast(v[2] + bb[2]); o0.w = gelu_fast(v[3] + bb[3]);
        o1.x = gelu_fast(v[4] + bb[4]); o1.y = gelu_fast(v[5] + bb[5]);
        o1.z = gelu_fast(v[6] + bb[6]); o1.w = gelu_fast(v[7] + bb[7]);
        float* op = g_u + (size_t)(r0 + tr*4 + i) * 64 + tc * 8;
        *(float4*)(op)     = o0;
        *(float4*)(op + 4) = o1;
    }
}

// ============================================================
// K2: per-chunk local scan -> final states; 8-way n-split.
// 512 threads = (nq 0..7) x (h 0..63); each thread: 2 complex
// states (ONE f32x2 pair). ~28 regs -> occupancy at warp cap.
// ============================================================
__global__ __launch_bounds__(512) void k_scan1()
{
    int bc  = blockIdx.x;           // b*NC + c
    int tid = threadIdx.x;
    int h   = tid & 63;
    int nq  = tid >> 6;             // 0..7
    int pb  = h * NSx + nq * 2;

    float wr0 = g_wre[pb], wr1 = g_wre[pb + 1];
    float wi0 = g_wim[pb], wi1 = g_wim[pb + 1];
    ull wre  = pk(wr0, wr1);
    ull wim  = pk(wi0, wi1);
    ull nwim = pk(-wi0, -wi1);
    ull sre = 0ull, sim = 0ull;

    const float* up = g_u + (size_t)bc * CHx * Hx + h;
    for (int lb = 0; lb < CHx; lb += 8) {
        float uu[8];
        #pragma unroll
        for (int j = 0; j < 8; j++) uu[j] = up[(size_t)(lb + j) * Hx];
        #pragma unroll
        for (int j = 0; j < 8; j++) {
            ull u2 = pk(uu[j], uu[j]);
            ull tre = fma2(nwim, sim, u2);
            ull nre = fma2(wre,  sre, tre);
            ull tt  = mul2(wim,  sre);
            ull nim = fma2(wre,  sim, tt);
            sre = nre; sim = nim;
        }
    }
    int sb = (bc * Hx + h) * NSx + nq * 2;
    *(ull*)(g_st_re + sb) = sre;
    *(ull*)(g_st_im + sb) = sim;
}

// ============================================================
// K3: serial carry scan across chunks — batched loads (MLP=16)
// ============================================================
__global__ __launch_bounds__(128) void k_carry()
{
    int id = blockIdx.x * blockDim.x + threadIdx.x;   // B*H*NS = 16384
    int b  = id >> 10;
    int hn = id & 1023;
    float wr = g_wcre[hn], wi = g_wcim[hn];
    float cr = 0.f, ci = 0.f;
    int base = b * NCx * (Hx * NSx) + hn;

    for (int cb = 0; cb < NCx; cb += 8) {
        float lr[8], li[8];
        #pragma unroll
        for (int j = 0; j < 8; j++) {
            int idx = base + (cb + j) * (Hx * NSx);
            lr[j] = g_st_re[idx];
            li[j] = g_st_im[idx];
        }
        #pragma unroll
        for (int j = 0; j < 8; j++) {
            int idx = base + (cb + j) * (Hx * NSx);
            g_ca_re[idx] = cr;
            g_ca_im[idx] = ci;
            float nr = fmaf(wr, cr, fmaf(-wi, ci, lr[j]));
            float ni = fmaf(wr, ci, fmaf( wi, cr, li[j]));
            cr = nr; ci = ni;
        }
    }
}

// ============================================================
// K4: seeded re-scan + D + FiLM + gelu + x-gate; 4-way n-split.
// 256 threads: h = tid>>2, nq = tid&3 (4 complex states each).
// Quad lanes adjacent in-warp -> butterfly shfl (xor 1, xor 2).
// ============================================================
__global__ __launch_bounds__(256) void k_scan2(const float* __restrict__ x,
                                               const float* __restrict__ Dv,
                                               float* __restrict__ out)
{
    int bc  = blockIdx.x;
    int tid = threadIdx.x;
    int h   = tid >> 2;
    int nq  = tid & 3;
    int b   = bc / NCx;
    int pb  = h * NSx + nq * 4;            // 4 states = 2 ull pairs
    int cb  = (bc * Hx + h) * NSx + nq * 4;

    ull wre[2], wim[2], nwim[2], kre[2], kim[2], sre[2], sim[2];
    #pragma unroll
    for (int p = 0; p < 2; p++) {
        float wr0 = g_wre[pb + 2*p],  wr1 = g_wre[pb + 2*p + 1];
        float wi0 = g_wim[pb + 2*p],  wi1 = g_wim[pb + 2*p + 1];
        wre[p]  = pk(wr0, wr1);
        wim[p]  = pk(wi0, wi1);
        nwim[p] = pk(-wi0, -wi1);
        kre[p]  = pk(g_c2re[pb + 2*p], g_c2re[pb + 2*p + 1]);
        kim[p]  = pk(g_c2im[pb + 2*p], g_c2im[pb + 2*p + 1]);
        sre[p]  = *(const ull*)(g_ca_re + cb + 2*p);
        sim[p]  = *(const ull*)(g_ca_im + cb + 2*p);
    }
    float Dh  = Dv[h];
    float gam = g_gam[b*Hx + h];
    float bet = g_bet[b*Hx + h];

    size_t base = (size_t)bc * CHx * Hx + h;
    const float* up = g_u + base;
    const float* xp = x + base;
    float*       op = out + base;

    for (int lb = 0; lb < CHx; lb += 8) {
        float uu[8], xx[8];
        #pragma unroll
        for (int j = 0; j < 8; j++) {
            uu[j] = up[(size_t)(lb + j) * Hx];
            xx[j] = xp[(size_t)(lb + j) * Hx];
        }
        #pragma unroll
        for (int j = 0; j < 8; j++) {
            float uv = uu[j];
            ull u2 = pk(uv, uv);
            ull ar = 0ull, ai = 0ull;
            #pragma unroll
            for (int p = 0; p < 2; p++) {
                ull tre = fma2(nwim[p], sim[p], u2);
                ull nre = fma2(wre[p],  sre[p], tre);
                ull t   = mul2(wim[p],  sre[p]);
                ull nim = fma2(wre[p],  sim[p], t);
                sre[p] = nre; sim[p] = nim;
                ar = fma2(kre[p], nre, ar);
                ai = fma2(kim[p], nim, ai);
            }
            ull  sv = add2(ar, ai);
            float slo, shi;
            upk(sv, slo, shi);
            float part = slo + shi;                          // this lane's quarter-sum
            part += __shfl_xor_sync(0xffffffffu, part, 1);
            part += __shfl_xor_sync(0xffffffffu, part, 2);
            if (nq == 0) {
                float y = fmaf(Dh, uv, part);
                float z = fmaf(y, gam, bet);
                op[(size_t)(lb + j) * Hx] = xx[j] * gelu_fast(z);
            }
        }
    }
}

// ============================================================
extern "C" void kernel_launch(void* const* d_in, const int* in_sizes, int n_in,
                              void* d_out, int out_size)
{
    const float* x       = (const float*)d_in[0];
    const float* cp      = (const float*)d_in[1];
    const float* W0      = (const float*)d_in[2];
    const float* b0      = (const float*)d_in[3];
    const float* W1      = (const float*)d_in[4];
    const float* b1      = (const float*)d_in[5];
    const float* W2      = (const float*)d_in[6];
    const float* b2      = (const float*)d_in[7];
    const float* W_lin   = (const float*)d_in[8];
    const float* b_lin   = (const float*)d_in[9];
    const float* log_dt  = (const float*)d_in[10];
    const float* A_re    = (const float*)d_in[11];
    const float* A_im    = (const float*)d_in[12];
    const float* C_re    = (const float*)d_in[13];
    const float* C_im    = (const float*)d_in[14];
    const float* Dv      = (const float*)d_in[15];
    const float* W_film  = (const float*)d_in[16];
    const float* b_film  = (const float*)d_in[17];
    float* out = (float*)d_out;

    k_setup<<<1, 1024>>>(cp, W0, b0, W1, b1, W2, b2,
                         log_dt, A_re, A_im, C_re, C_im, W_film, b_film);
    k_linear<<<(Bx * Lx) / 64, 128>>>(x, W_lin, b_lin);
    k_scan1<<<Bx * NCx, 512>>>();
    k_carry<<<(Bx * Hx * NSx) / 128, 128>>>();
    k_scan2<<<Bx * NCx, 256>>>(x, Dv, out);
}

// round 13
// speedup vs baseline: 1.2448x; 1.2448x over previous
#include <cuda_runtime.h>
#include <math.h>

#define Bx  16
#define Lx  32768
#define Hx  64
#define NSx 16
#define DMx 32
#define CHx 256
#define NCx (Lx/CHx)   // 128 chunks

typedef unsigned long long ull;

// ---- scratch (static device arrays: allocation-free) ----
__device__ __align__(16) float g_u[Bx*Lx*Hx];             // gelu(x@W_lin+b), [B,L,H]
__device__ __align__(16) float g_st_re[Bx*NCx*Hx*NSx];    // per-chunk local final states
__device__ __align__(16) float g_st_im[Bx*NCx*Hx*NSx];
__device__ __align__(16) float g_ca_re[Bx*NCx*Hx*NSx];    // carry-in per chunk
__device__ __align__(16) float g_ca_im[Bx*NCx*Hx*NSx];
__device__ float g_wre[Hx*NSx], g_wim[Hx*NSx];     // w = exp(dt*A)
__device__ float g_c2re[Hx*NSx], g_c2im[Hx*NSx];   // 2*Re/-2*Im of C*(w-1)/A
__device__ float g_wcre[Hx*NSx], g_wcim[Hx*NSx];   // w^CH
__device__ float g_gam[Bx*Hx], g_bet[Bx*Hx];       // FiLM params

// ---- packed f32x2 helpers (sm_103a) ----
__device__ __forceinline__ ull pk(float lo, float hi) {
    ull r; asm("mov.b64 %0, {%1,%2};" : "=l"(r) : "f"(lo), "f"(hi)); return r;
}
__device__ __forceinline__ void upk(ull v, float& lo, float& hi) {
    asm("mov.b64 {%0,%1}, %2;" : "=f"(lo), "=f"(hi) : "l"(v));
}
__device__ __forceinline__ ull fma2(ull a, ull b, ull c) {
    ull d; asm("fma.rn.f32x2 %0, %1, %2, %3;" : "=l"(d) : "l"(a), "l"(b), "l"(c)); return d;
}
__device__ __forceinline__ ull mul2(ull a, ull b) {
    ull d; asm("mul.rn.f32x2 %0, %1, %2;" : "=l"(d) : "l"(a), "l"(b)); return d;
}
__device__ __forceinline__ ull add2(ull a, ull b) {
    ull d; asm("add.rn.f32x2 %0, %1, %2;" : "=l"(d) : "l"(a), "l"(b)); return d;
}

__device__ __forceinline__ float gelu_t(float x) {
    float x3 = x * x * x;
    float t  = tanhf(0.7978845608028654f * fmaf(0.044715f, x3, x));
    return 0.5f * x * (1.0f + t);
}
__device__ __forceinline__ float gelu_fast(float x) {
    float x3  = x * x * x;
    float arg = 0.7978845608028654f * fmaf(0.044715f, x3, x);
    float t;
    asm("tanh.approx.f32 %0, %1;" : "=f"(t) : "f"(arg));
    return 0.5f * x * (1.0f + t);
}

// ============================================================
// K0: SSM constants (fp64 setup) + cond-MLP + FiLM projection
// ============================================================
__global__ void k_setup(const float* __restrict__ cp,
                        const float* __restrict__ W0, const float* __restrict__ b0,
                        const float* __restrict__ W1, const float* __restrict__ b1,
                        const float* __restrict__ W2, const float* __restrict__ b2,
                        const float* __restrict__ log_dt,
                        const float* __restrict__ A_re, const float* __restrict__ A_im,
                        const float* __restrict__ C_re, const float* __restrict__ C_im,
                        const float* __restrict__ W_film, const float* __restrict__ b_film)
{
    int tid = threadIdx.x;

    if (tid < Hx * NSx) {
        int h = tid / NSx;
        double dt = exp((double)log_dt[h]);
        double ar = (double)A_re[tid], ai = (double)A_im[tid];
        double dr = dt * ar, di = dt * ai;
        double er = exp(dr);
        double wr = er * cos(di), wi = er * sin(di);
        g_wre[tid] = (float)wr;
        g_wim[tid] = (float)wi;
        double Er = wr - 1.0, Ei = wi;
        double a2 = ar * ar + ai * ai;
        double qr = (Er * ar + Ei * ai) / a2;
        double qi = (Ei * ar - Er * ai) / a2;
        double cr = (double)C_re[tid], ci = (double)C_im[tid];
        double Ctr = cr * qr - ci * qi;
        double Cti = cr * qi + ci * qr;
        g_c2re[tid] = (float)( 2.0 * Ctr);
        g_c2im[tid] = (float)(-2.0 * Cti);
        double drC = dr * (double)CHx, diC = di * (double)CHx;
        double erC = exp(drC);
        g_wcre[tid] = (float)(erC * cos(diC));
        g_wcim[tid] = (float)(erC * sin(diC));
    }

    __shared__ float s1[Bx * DMx];
    __shared__ float s2[Bx * DMx];
    if (tid < Bx * DMx) {
        int b = tid / DMx, d = tid % DMx;
        float v = b0[d] + cp[b*2 + 0] * W0[0*DMx + d] + cp[b*2 + 1] * W0[1*DMx + d];
        s1[tid] = gelu_t(v);
    }
    __syncthreads();
    if (tid < Bx * DMx) {
        int b = tid / DMx, d = tid % DMx;
        float v = b1[d];
        #pragma unroll
        for (int k = 0; k < DMx; k++) v = fmaf(s1[b*DMx + k], W1[k*DMx + d], v);
        s2[tid] = gelu_t(v);
    }
    __syncthreads();
    if (tid < Bx * DMx) {
        int b = tid / DMx, d = tid % DMx;
        float v = b2[d];
        #pragma unroll
        for (int k = 0; k < DMx; k++) v = fmaf(s2[b*DMx + k], W2[k*DMx + d], v);
        s1[tid] = gelu_t(v);
    }
    __syncthreads();
    for (int j = tid; j < Bx * 2 * Hx; j += blockDim.x) {
        int b = j / (2 * Hx), o = j % (2 * Hx);
        float v = b_film[o];
        #pragma unroll
        for (int k = 0; k < DMx; k++) v = fmaf(s1[b*DMx + k], W_film[k*2*Hx + o], v);
        if (o < Hx) g_gam[b*Hx + o] = v;
        else        g_bet[b*Hx + (o - Hx)] = v;
    }
}

// ============================================================
// K1: u = gelu(x @ W_lin + b_lin) — 64x64 tile, f32x2 packed FMA
// ============================================================
__global__ __launch_bounds__(128) void k_linear(const float* __restrict__ x,
                                                const float* __restrict__ Wl,
                                                const float* __restrict__ bl)
{
    __shared__ float sxT[64][68];
    __shared__ __align__(16) float sW[64 * 64];
    int tid = threadIdx.x;
    int r0  = blockIdx.x * 64;

    #pragma unroll
    for (int it = 0; it < 8; it++) {
        int i = tid + it * 128;
        *(float4*)(sW + i * 4) = *(const float4*)(Wl + i * 4);
    }
    #pragma unroll
    for (int it = 0; it < 8; it++) {
        int idx = tid + it * 128;
        int row = idx >> 4;
        int kg  = idx & 15;
        float4 v = *(const float4*)(x + (size_t)(r0 + row) * 64 + kg * 4);
        sxT[kg*4 + 0][row] = v.x;
        sxT[kg*4 + 1][row] = v.y;
        sxT[kg*4 + 2][row] = v.z;
        sxT[kg*4 + 3][row] = v.w;
    }
    __syncthreads();

    int tr = tid >> 3;
    int tc = tid & 7;
    ull acc[4][4];
    #pragma unroll
    for (int i = 0; i < 4; i++)
        #pragma unroll
        for (int j = 0; j < 4; j++) acc[i][j] = 0ull;

    #pragma unroll 4
    for (int k = 0; k < 64; k++) {
        float4 a = *(const float4*)(&sxT[k][tr * 4]);
        ull aa[4];
        aa[0] = pk(a.x, a.x); aa[1] = pk(a.y, a.y);
        aa[2] = pk(a.z, a.z); aa[3] = pk(a.w, a.w);
        const float* wrow = &sW[k * 64 + tc * 8];
        ull w0 = *(const ull*)(wrow + 0);
        ull w1 = *(const ull*)(wrow + 2);
        ull w2 = *(const ull*)(wrow + 4);
        ull w3 = *(const ull*)(wrow + 6);
        #pragma unroll
        for (int i = 0; i < 4; i++) {
            acc[i][0] = fma2(aa[i], w0, acc[i][0]);
            acc[i][1] = fma2(aa[i], w1, acc[i][1]);
            acc[i][2] = fma2(aa[i], w2, acc[i][2]);
            acc[i][3] = fma2(aa[i], w3, acc[i][3]);
        }
    }

    float bb[8];
    #pragma unroll
    for (int j = 0; j < 8; j++) bb[j] = bl[tc * 8 + j];
    #pragma unroll
    for (int i = 0; i < 4; i++) {
        float v[8];
        #pragma unroll
        for (int j = 0; j < 4; j++) upk(acc[i][j], v[2*j], v[2*j+1]);
        float4 o0, o1;
        o0.x = gelu_fast(v[0] + bb[0]); o0.y = gelu_fast(v[1] + bb[1]);
        o0.z = gelu_fast(v[2] + bb[2]); o0.w = gelu_fast(v[3] + bb[3]);
        o1.x = gelu_fast(v[4] + bb[4]); o1.y = gelu_fast(v[5] + bb[5]);
        o1.z = gelu_fast(v[6] + bb[6]); o1.w = gelu_fast(v[7] + bb[7]);
        float* op = g_u + (size_t)(r0 + tr*4 + i) * 64 + tc * 8;
        *(float4*)(op)     = o0;
        *(float4*)(op + 4) = o1;
    }
}

// ============================================================
// K2: per-chunk local scan; SMEM-staged u, 4-way n-split.
// 256 threads = (nq 0..3) x (h 0..63). u tile loaded ONCE
// (coalesced float4), scan reads LDS (conflict-free: lanes span h).
// ============================================================
__global__ __launch_bounds__(256) void k_scan1()
{
    __shared__ __align__(16) float su[64 * 64];   // 16KB tile [l][h]
    int bc  = blockIdx.x;           // b*NC + c
    int tid = threadIdx.x;
    int h   = tid & 63;
    int nq  = tid >> 6;             // 0..3
    int pb  = h * NSx + nq * 4;

    ull wre2[2], wim2[2], nwim2[2], sre2[2], sim2[2];
    #pragma unroll
    for (int p = 0; p < 2; p++) {
        float wr0 = g_wre[pb + 2*p], wr1 = g_wre[pb + 2*p + 1];
        float wi0 = g_wim[pb + 2*p], wi1 = g_wim[pb + 2*p + 1];
        wre2[p]  = pk(wr0, wr1);
        wim2[p]  = pk(wi0, wi1);
        nwim2[p] = pk(-wi0, -wi1);
        sre2[p] = 0ull; sim2[p] = 0ull;
    }

    const float* up = g_u + (size_t)bc * CHx * Hx;
    #pragma unroll 1
    for (int t = 0; t < 4; t++) {
        // cooperative tile load: 4096 floats = 1024 float4
        #pragma unroll
        for (int it = 0; it < 4; it++) {
            int idx = tid + it * 256;
            *(float4*)(su + idx * 4) =
                *(const float4*)(up + (size_t)t * 64 * Hx + idx * 4);
        }
        __syncthreads();

        for (int lb = 0; lb < 64; lb += 8) {
            float uu[8];
            #pragma unroll
            for (int j = 0; j < 8; j++) uu[j] = su[(lb + j) * 64 + h];
            #pragma unroll
            for (int j = 0; j < 8; j++) {
                ull u2 = pk(uu[j], uu[j]);
                #pragma unroll
                for (int p = 0; p < 2; p++) {
                    ull tre = fma2(nwim2[p], sim2[p], u2);
                    ull nre = fma2(wre2[p],  sre2[p], tre);
                    ull tt  = mul2(wim2[p],  sre2[p]);
                    ull nim = fma2(wre2[p],  sim2[p], tt);
                    sre2[p] = nre; sim2[p] = nim;
                }
            }
        }
        __syncthreads();
    }
    int sb = (bc * Hx + h) * NSx + nq * 4;
    #pragma unroll
    for (int p = 0; p < 2; p++) {
        *(ull*)(g_st_re + sb + 2*p) = sre2[p];
        *(ull*)(g_st_im + sb + 2*p) = sim2[p];
    }
}

// ============================================================
// K3: serial carry scan across chunks — batched loads (MLP=16)
// ============================================================
__global__ __launch_bounds__(128) void k_carry()
{
    int id = blockIdx.x * blockDim.x + threadIdx.x;   // B*H*NS = 16384
    int b  = id >> 10;
    int hn = id & 1023;
    float wr = g_wcre[hn], wi = g_wcim[hn];
    float cr = 0.f, ci = 0.f;
    int base = b * NCx * (Hx * NSx) + hn;

    for (int cb = 0; cb < NCx; cb += 8) {
        float lr[8], li[8];
        #pragma unroll
        for (int j = 0; j < 8; j++) {
            int idx = base + (cb + j) * (Hx * NSx);
            lr[j] = g_st_re[idx];
            li[j] = g_st_im[idx];
        }
        #pragma unroll
        for (int j = 0; j < 8; j++) {
            int idx = base + (cb + j) * (Hx * NSx);
            g_ca_re[idx] = cr;
            g_ca_im[idx] = ci;
            float nr = fmaf(wr, cr, fmaf(-wi, ci, lr[j]));
            float ni = fmaf(wr, ci, fmaf( wi, cr, li[j]));
            cr = nr; ci = ni;
        }
    }
}

// ============================================================
// K4: seeded re-scan + D + FiLM + gelu + x-gate.
// 256 threads: h = tid>>2, nq = tid&3 (quad lanes adjacent for
// butterfly shfl). u staged in SMEM (loaded once, LDS broadcast
// across the quad); x loaded/stored only by nq==0 lanes.
// ============================================================
__global__ __launch_bounds__(256) void k_scan2(const float* __restrict__ x,
                                               const float* __restrict__ Dv,
                                               float* __restrict__ out)
{
    __shared__ __align__(16) float su[64 * 64];   // 16KB tile [l][h]
    int bc  = blockIdx.x;
    int tid = threadIdx.x;
    int h   = tid >> 2;
    int nq  = tid & 3;
    int b   = bc / NCx;
    int pb  = h * NSx + nq * 4;            // 4 states = 2 ull pairs
    int cb  = (bc * Hx + h) * NSx + nq * 4;

    ull wre[2], wim[2], nwim[2], kre[2], kim[2], sre[2], sim[2];
    #pragma unroll
    for (int p = 0; p < 2; p++) {
        float wr0 = g_wre[pb + 2*p],  wr1 = g_wre[pb + 2*p + 1];
        float wi0 = g_wim[pb + 2*p],  wi1 = g_wim[pb + 2*p + 1];
        wre[p]  = pk(wr0, wr1);
        wim[p]  = pk(wi0, wi1);
        nwim[p] = pk(-wi0, -wi1);
        kre[p]  = pk(g_c2re[pb + 2*p], g_c2re[pb + 2*p + 1]);
        kim[p]  = pk(g_c2im[pb + 2*p], g_c2im[pb + 2*p + 1]);
        sre[p]  = *(const ull*)(g_ca_re + cb + 2*p);
        sim[p]  = *(const ull*)(g_ca_im + cb + 2*p);
    }
    float Dh  = Dv[h];
    float gam = g_gam[b*Hx + h];
    float bet = g_bet[b*Hx + h];

    const float* up = g_u + (size_t)bc * CHx * Hx;
    const float* xp = x   + (size_t)bc * CHx * Hx + h;
    float*       op = out + (size_t)bc * CHx * Hx + h;

    #pragma unroll 1
    for (int t = 0; t < 4; t++) {
        #pragma unroll
        for (int it = 0; it < 4; it++) {
            int idx = tid + it * 256;
            *(float4*)(su + idx * 4) =
                *(const float4*)(up + (size_t)t * 64 * Hx + idx * 4);
        }
        __syncthreads();

        for (int lb = 0; lb < 64; lb += 8) {
            float uu[8], xx[8];
            #pragma unroll
            for (int j = 0; j < 8; j++) uu[j] = su[(lb + j) * 64 + h];
            if (nq == 0) {
                #pragma unroll
                for (int j = 0; j < 8; j++)
                    xx[j] = xp[(size_t)(t * 64 + lb + j) * Hx];
            }
            #pragma unroll
            for (int j = 0; j < 8; j++) {
                float uv = uu[j];
                ull u2 = pk(uv, uv);
                ull ar = 0ull, ai = 0ull;
                #pragma unroll
                for (int p = 0; p < 2; p++) {
                    ull tre = fma2(nwim[p], sim[p], u2);
                    ull nre = fma2(wre[p],  sre[p], tre);
                    ull tt  = mul2(wim[p],  sre[p]);
                    ull nim = fma2(wre[p],  sim[p], tt);
                    sre[p] = nre; sim[p] = nim;
                    ar = fma2(kre[p], nre, ar);
                    ai = fma2(kim[p], nim, ai);
                }
                ull  sv = add2(ar, ai);
                float slo, shi;
                upk(sv, slo, shi);
                float part = slo + shi;
                part += __shfl_xor_sync(0xffffffffu, part, 1);
                part += __shfl_xor_sync(0xffffffffu, part, 2);
                if (nq == 0) {
                    float y = fmaf(Dh, uv, part);
                    float z = fmaf(y, gam, bet);
                    op[(size_t)(t * 64 + lb + j) * Hx] = xx[j] * gelu_fast(z);
                }
            }
        }
        __syncthreads();
    }
}

// ============================================================
extern "C" void kernel_launch(void* const* d_in, const int* in_sizes, int n_in,
                              void* d_out, int out_size)
{
    const float* x       = (const float*)d_in[0];
    const float* cp      = (const float*)d_in[1];
    const float* W0      = (const float*)d_in[2];
    const float* b0      = (const float*)d_in[3];
    const float* W1      = (const float*)d_in[4];
    const float* b1      = (const float*)d_in[5];
    const float* W2      = (const float*)d_in[6];
    const float* b2      = (const float*)d_in[7];
    const float* W_lin   = (const float*)d_in[8];
    const float* b_lin   = (const float*)d_in[9];
    const float* log_dt  = (const float*)d_in[10];
    const float* A_re    = (const float*)d_in[11];
    const float* A_im    = (const float*)d_in[12];
    const float* C_re    = (const float*)d_in[13];
    const float* C_im    = (const float*)d_in[14];
    const float* Dv      = (const float*)d_in[15];
    const float* W_film  = (const float*)d_in[16];
    const float* b_film  = (const float*)d_in[17];
    float* out = (float*)d_out;

    k_setup<<<1, 1024>>>(cp, W0, b0, W1, b1, W2, b2,
                         log_dt, A_re, A_im, C_re, C_im, W_film, b_film);
    k_linear<<<(Bx * Lx) / 64, 128>>>(x, W_lin, b_lin);
    k_scan1<<<Bx * NCx, 256>>>();
    k_carry<<<(Bx * Hx * NSx) / 128, 128>>>();
    k_scan2<<<Bx * NCx, 256>>>(x, Dv, out);
}